// round 1
// baseline (speedup 1.0000x reference)
#include <cuda_runtime.h>
#include <math.h>

// Problem dims
#define DS 1024          // S (source len)
#define DN 64            // N (batch)
#define DH 1024          // H (hidden)
#define DI 1024          // INPUT_SIZE
#define DM (DS * DN)     // 65536 rows of the big GEMM

// GEMM tiling
#define BM 128
#define BI 128
#define BK 16
#define KT (DH / BK)     // 64 k-tiles
#define ITILES (DI / BI) // 8 i-tiles

// Scratch (no cudaMalloc allowed)
__device__ float g_u[DN * DI];     // u[n,i] = b1+b2 + hidden_d[n]·W1[i]
__device__ float g_a[DM];          // raw scores a[s*N+n]
__device__ float g_alpha[DM];      // fallback alpha storage

// ---------------------------------------------------------------------------
// Kernel 1: u[n][i] = b1[i] + b2[i] + dot(hidden_d[n,:], W1[i,:])
// 64 blocks (one per n), 256 threads.
// ---------------------------------------------------------------------------
__global__ void k_u(const float* __restrict__ hd, const float* __restrict__ W1,
                    const float* __restrict__ b1, const float* __restrict__ b2) {
    __shared__ float sh[DH];
    const int n = blockIdx.x;
    for (int h = threadIdx.x; h < DH; h += blockDim.x) sh[h] = hd[n * DH + h];
    __syncthreads();
    for (int i = threadIdx.x; i < DI; i += blockDim.x) {
        const float4* w = reinterpret_cast<const float4*>(W1 + (size_t)i * DH);
        const float4* sv = reinterpret_cast<const float4*>(sh);
        float ax = 0.f, ay = 0.f, az = 0.f, aw = 0.f;
#pragma unroll 4
        for (int h4 = 0; h4 < DH / 4; h4++) {
            float4 a = sv[h4];
            float4 b = w[h4];
            ax = fmaf(a.x, b.x, ax);
            ay = fmaf(a.y, b.y, ay);
            az = fmaf(a.z, b.z, az);
            aw = fmaf(a.w, b.w, aw);
        }
        g_u[n * DI + i] = (ax + ay) + (az + aw) + b1[i] + b2[i];
    }
}

// ---------------------------------------------------------------------------
// Kernel 2: fused  a[m] = b3 + sum_i W3[i] * tanh(u[m%N, i] + A[m,:]·W2[i,:])
// A = out_e viewed as [M=65536, K=1024] row-major (K contiguous).
// 128x128 CTA tile, 8x8 per-thread microtile, double-buffered smem.
// Each CTA owns 128 m-rows and loops over all 8 i-tiles, accumulating the
// W3-weighted tanh reduction in registers -> only a[] hits memory.
// ---------------------------------------------------------------------------
__global__ __launch_bounds__(256, 2) void k_main(
    const float* __restrict__ A, const float* __restrict__ W2,
    const float* __restrict__ W3, const float* __restrict__ b3) {
    __shared__ float As[2][BK][BM];
    __shared__ float Bs[2][BK][BI];

    const int tid = threadIdx.x;
    const int r = tid >> 4;   // 0..15 -> row group (8 rows each)
    const int c = tid & 15;   // 0..15 -> col group (8 cols each)
    const int m0 = blockIdx.x * BM;

    // gmem->smem load mapping: 512 float4 per tile, 2 per thread
    const int row0 = tid >> 2;          // 0..63
    const int q0 = tid & 3;             // which float4 inside the BK=16 row
    const int row1 = row0 + 64;         // (tid+256)>>2

    float part[8];
#pragma unroll
    for (int j = 0; j < 8; j++) part[j] = 0.f;

    const size_t arow0 = (size_t)(m0 + row0) * DH;
    const size_t arow1 = (size_t)(m0 + row1) * DH;

    for (int it = 0; it < ITILES; ++it) {
        const int i0 = it * BI;
        float acc[8][8];
#pragma unroll
        for (int j = 0; j < 8; j++)
#pragma unroll
            for (int l = 0; l < 8; l++) acc[j][l] = 0.f;

        // initial k-tile -> buffer 0
        {
            float4 a0 = *reinterpret_cast<const float4*>(A + arow0 + q0 * 4);
            float4 a1 = *reinterpret_cast<const float4*>(A + arow1 + q0 * 4);
            float4 w0 = *reinterpret_cast<const float4*>(W2 + (size_t)(i0 + row0) * DH + q0 * 4);
            float4 w1 = *reinterpret_cast<const float4*>(W2 + (size_t)(i0 + row1) * DH + q0 * 4);
            __syncthreads();  // previous i-tile done with buffers
            As[0][q0 * 4 + 0][row0] = a0.x; As[0][q0 * 4 + 1][row0] = a0.y;
            As[0][q0 * 4 + 2][row0] = a0.z; As[0][q0 * 4 + 3][row0] = a0.w;
            As[0][q0 * 4 + 0][row1] = a1.x; As[0][q0 * 4 + 1][row1] = a1.y;
            As[0][q0 * 4 + 2][row1] = a1.z; As[0][q0 * 4 + 3][row1] = a1.w;
            Bs[0][q0 * 4 + 0][row0] = w0.x; Bs[0][q0 * 4 + 1][row0] = w0.y;
            Bs[0][q0 * 4 + 2][row0] = w0.z; Bs[0][q0 * 4 + 3][row0] = w0.w;
            Bs[0][q0 * 4 + 0][row1] = w1.x; Bs[0][q0 * 4 + 1][row1] = w1.y;
            Bs[0][q0 * 4 + 2][row1] = w1.z; Bs[0][q0 * 4 + 3][row1] = w1.w;
        }
        __syncthreads();

        for (int kt = 0; kt < KT; ++kt) {
            const int cur = kt & 1;
            const bool pf = (kt + 1 < KT);
            float4 a0, a1, w0, w1;
            if (pf) {
                const int k0 = (kt + 1) * BK;
                a0 = *reinterpret_cast<const float4*>(A + arow0 + k0 + q0 * 4);
                a1 = *reinterpret_cast<const float4*>(A + arow1 + k0 + q0 * 4);
                w0 = *reinterpret_cast<const float4*>(W2 + (size_t)(i0 + row0) * DH + k0 + q0 * 4);
                w1 = *reinterpret_cast<const float4*>(W2 + (size_t)(i0 + row1) * DH + k0 + q0 * 4);
            }
#pragma unroll
            for (int k = 0; k < BK; k++) {
                float af[8], bf[8];
                *reinterpret_cast<float4*>(&af[0]) =
                    *reinterpret_cast<const float4*>(&As[cur][k][r * 8]);
                *reinterpret_cast<float4*>(&af[4]) =
                    *reinterpret_cast<const float4*>(&As[cur][k][r * 8 + 4]);
                *reinterpret_cast<float4*>(&bf[0]) =
                    *reinterpret_cast<const float4*>(&Bs[cur][k][c * 8]);
                *reinterpret_cast<float4*>(&bf[4]) =
                    *reinterpret_cast<const float4*>(&Bs[cur][k][c * 8 + 4]);
#pragma unroll
                for (int j = 0; j < 8; j++)
#pragma unroll
                    for (int l = 0; l < 8; l++)
                        acc[j][l] = fmaf(af[j], bf[l], acc[j][l]);
            }
            if (pf) {
                const int nxt = cur ^ 1;
                __syncthreads();  // everyone done reading buffers
                As[nxt][q0 * 4 + 0][row0] = a0.x; As[nxt][q0 * 4 + 1][row0] = a0.y;
                As[nxt][q0 * 4 + 2][row0] = a0.z; As[nxt][q0 * 4 + 3][row0] = a0.w;
                As[nxt][q0 * 4 + 0][row1] = a1.x; As[nxt][q0 * 4 + 1][row1] = a1.y;
                As[nxt][q0 * 4 + 2][row1] = a1.z; As[nxt][q0 * 4 + 3][row1] = a1.w;
                Bs[nxt][q0 * 4 + 0][row0] = w0.x; Bs[nxt][q0 * 4 + 1][row0] = w0.y;
                Bs[nxt][q0 * 4 + 2][row0] = w0.z; Bs[nxt][q0 * 4 + 3][row0] = w0.w;
                Bs[nxt][q0 * 4 + 0][row1] = w1.x; Bs[nxt][q0 * 4 + 1][row1] = w1.y;
                Bs[nxt][q0 * 4 + 2][row1] = w1.z; Bs[nxt][q0 * 4 + 3][row1] = w1.w;
                __syncthreads();
            }
        }

        // fused epilogue: + u, tanh, W3-weighted reduce over i
        float w3v[8];
#pragma unroll
        for (int l = 0; l < 8; l++) w3v[l] = W3[i0 + c * 8 + l];
#pragma unroll
        for (int j = 0; j < 8; j++) {
            const int m = m0 + r * 8 + j;
            const float* ur = g_u + (size_t)(m & (DN - 1)) * DI + i0 + c * 8;
            float s = 0.f;
#pragma unroll
            for (int l = 0; l < 8; l++)
                s += w3v[l] * tanhf(acc[j][l] + ur[l]);
            part[j] += s;
        }
    }

    // reduce the 16 c-groups per row (16 consecutive lanes share r)
    const float bb3 = b3[0];
#pragma unroll
    for (int j = 0; j < 8; j++) {
        float v = part[j];
        v += __shfl_xor_sync(0xffffffffu, v, 8);
        v += __shfl_xor_sync(0xffffffffu, v, 4);
        v += __shfl_xor_sync(0xffffffffu, v, 2);
        v += __shfl_xor_sync(0xffffffffu, v, 1);
        if (c == 0) g_a[m0 + r * 8 + j] = v + bb3;
    }
}

// ---------------------------------------------------------------------------
// Kernel 3: softmax over S per column n. 64 blocks, 256 threads, 4 vals/thread.
// ---------------------------------------------------------------------------
__global__ void k_softmax(float* __restrict__ alpha) {
    const int n = blockIdx.x;
    const int t = threadIdx.x;
    __shared__ float sred[16];

    float loc[4];
    float mx = -1e30f;
#pragma unroll
    for (int q = 0; q < 4; q++) {
        loc[q] = g_a[(t + q * 256) * DN + n];
        mx = fmaxf(mx, loc[q]);
    }
#pragma unroll
    for (int off = 16; off; off >>= 1) mx = fmaxf(mx, __shfl_xor_sync(0xffffffffu, mx, off));
    if ((t & 31) == 0) sred[t >> 5] = mx;
    __syncthreads();
    if (t == 0) {
        float v = sred[0];
        for (int w = 1; w < 8; w++) v = fmaxf(v, sred[w]);
        sred[0] = v;
    }
    __syncthreads();
    mx = sred[0];

    float sum = 0.f;
#pragma unroll
    for (int q = 0; q < 4; q++) {
        loc[q] = expf(loc[q] - mx);
        sum += loc[q];
    }
#pragma unroll
    for (int off = 16; off; off >>= 1) sum += __shfl_xor_sync(0xffffffffu, sum, off);
    if ((t & 31) == 0) sred[8 + (t >> 5)] = sum;
    __syncthreads();
    if (t == 0) {
        float v = 0.f;
        for (int w = 0; w < 8; w++) v += sred[8 + w];
        sred[8] = v;
    }
    __syncthreads();
    const float inv = 1.0f / sred[8];
#pragma unroll
    for (int q = 0; q < 4; q++) alpha[(t + q * 256) * DN + n] = loc[q] * inv;
}

// ---------------------------------------------------------------------------
// Kernel 4: c[n,h] = sum_s alpha[s,n] * out_e[s,n,h].  grid (64 n, 4 h-chunks).
// ---------------------------------------------------------------------------
__global__ void k_ctx(const float* __restrict__ out_e, const float* __restrict__ alpha,
                      float* __restrict__ cdst) {
    const int n = blockIdx.x;
    const int h = blockIdx.y * 256 + threadIdx.x;
    __shared__ float sal[DS];
    for (int s = threadIdx.x; s < DS; s += 256) sal[s] = alpha[s * DN + n];
    __syncthreads();
    float a0 = 0.f, a1 = 0.f, a2 = 0.f, a3 = 0.f;
    const float* base = out_e + (size_t)n * DH + h;
    for (int s = 0; s < DS; s += 4) {
        a0 = fmaf(sal[s + 0], base[(size_t)(s + 0) * DN * DH], a0);
        a1 = fmaf(sal[s + 1], base[(size_t)(s + 1) * DN * DH], a1);
        a2 = fmaf(sal[s + 2], base[(size_t)(s + 2) * DN * DH], a2);
        a3 = fmaf(sal[s + 3], base[(size_t)(s + 3) * DN * DH], a3);
    }
    cdst[n * DH + h] = (a0 + a1) + (a2 + a3);
}

// ---------------------------------------------------------------------------
extern "C" void kernel_launch(void* const* d_in, const int* in_sizes, int n_in,
                              void* d_out, int out_size) {
    const float* out_e    = (const float*)d_in[0];
    const float* hidden_d = (const float*)d_in[1];
    const float* W1       = (const float*)d_in[2];
    const float* b1       = (const float*)d_in[3];
    const float* W2       = (const float*)d_in[4];
    const float* b2       = (const float*)d_in[5];
    const float* W3       = (const float*)d_in[6];
    const float* b3       = (const float*)d_in[7];
    float* out = (float*)d_out;

    // Output layout: c [N*H] then alpha [S*N] (tuple order from reference).
    float* cdst = out;
    float* alpha;
    if (out_size >= DN * DH + DM) {
        alpha = out + DN * DH;
    } else {
        void* p = nullptr;
        cudaGetSymbolAddress(&p, g_alpha);
        alpha = (float*)p;
    }

    k_u<<<DN, 256>>>(hidden_d, W1, b1, b2);
    k_main<<<DM / BM, 256>>>(out_e, W2, W3, b3);
    k_softmax<<<DN, 256>>>(alpha);
    k_ctx<<<dim3(DN, 4), 256>>>(out_e, alpha, cdst);
}

// round 3
// speedup vs baseline: 3.4077x; 3.4077x over previous
#include <cuda_runtime.h>
#include <cstdint>
#include <math.h>

// Problem dims
#define DS 1024
#define DN 64
#define DH 1024
#define DI 1024
#define DM (DS * DN)

// GEMM tiling
#define MT_CTA 128           // m rows per CTA
#define NT_CTA 256           // i cols per CTA
#define KC 32                // k floats per chunk
#define NCHUNK (DH / KC)     // 32

// Fragment-packed smem sizes (in floats/words)
#define AW 4096              // 4 ks * 8 mtiles * 32 lanes * 4 words
#define BW 8192              // 4 ks * 32 ntiles * 32 lanes * 2 words
#define STAGEW (AW + BW)     // 12288 words = 48KB
#define SMEM_WORDS (2 * STAGEW + 128)
#define SMEM_BYTES (SMEM_WORDS * 4)

// Scratch
__device__ float g_u[DI * DN];       // u transposed: [i][n]
__device__ float g_apart[4 * DM];    // per-i-quarter partial scores
__device__ float g_alpha_fallback[DM];

__device__ __forceinline__ float tanh_apx(float x) {
    float y;
    asm("tanh.approx.f32 %0, %1;" : "=f"(y) : "f"(x));
    return y;
}

__device__ __forceinline__ void mma_tf32(float* d, const uint32_t* a, const uint32_t* b) {
    asm volatile(
        "mma.sync.aligned.m16n8k8.row.col.f32.tf32.tf32.f32 "
        "{%0,%1,%2,%3}, {%4,%5,%6,%7}, {%8,%9}, {%0,%1,%2,%3};"
        : "+f"(d[0]), "+f"(d[1]), "+f"(d[2]), "+f"(d[3])
        : "r"(a[0]), "r"(a[1]), "r"(a[2]), "r"(a[3]), "r"(b[0]), "r"(b[1]));
}

// ---------------------------------------------------------------------------
// Kernel 1: u_t[i][n] = b1[i] + b2[i] + dot(hidden_d[n,:], W1[i,:])
// ---------------------------------------------------------------------------
__global__ void k_u(const float* __restrict__ hd, const float* __restrict__ W1,
                    const float* __restrict__ b1, const float* __restrict__ b2) {
    __shared__ float sh[DH];
    const int n = blockIdx.x;
    for (int h = threadIdx.x; h < DH; h += blockDim.x) sh[h] = hd[n * DH + h];
    __syncthreads();
    for (int i = threadIdx.x; i < DI; i += blockDim.x) {
        const float4* w = reinterpret_cast<const float4*>(W1 + (size_t)i * DH);
        const float4* sv = reinterpret_cast<const float4*>(sh);
        float ax = 0.f, ay = 0.f, az = 0.f, aw = 0.f;
#pragma unroll 4
        for (int h4 = 0; h4 < DH / 4; h4++) {
            float4 a = sv[h4];
            float4 b = w[h4];
            ax = fmaf(a.x, b.x, ax);
            ay = fmaf(a.y, b.y, ay);
            az = fmaf(a.z, b.z, az);
            aw = fmaf(a.w, b.w, aw);
        }
        g_u[i * DN + n] = (ax + ay) + (az + aw) + b1[i] + b2[i];
    }
}

// ---------------------------------------------------------------------------
// Kernel 2: mma.sync tf32 fused GEMM + tanh + W3 reduction.
// grid (4 i-quarters, 512 m-blocks), 256 threads.
// CTA: 128m x 256i, K=1024 in 32 chunks, double-buffered fragment-packed smem.
// Warp w: wm = w>>2 (m half), wn = w&3 (i quarter of 64) -> 64x64 warp tile.
// ---------------------------------------------------------------------------
__global__ __launch_bounds__(256, 1) void k_gemm(
    const float* __restrict__ A,    // out_e as [65536, 1024]
    const float* __restrict__ W2,   // [1024, 1024]
    const float* __restrict__ W3) {
    extern __shared__ float sm[];
    float* sacc = sm + 2 * STAGEW;

    const int tid = threadIdx.x;
    const int lane = tid & 31;
    const int wid = tid >> 5;
    const int wm = wid >> 2;   // 0..1
    const int wn = wid & 3;    // 0..3
    const int i0 = blockIdx.x * NT_CTA;
    const int m0 = blockIdx.y * MT_CTA;

    // loader mapping
    const int lrow = tid >> 3;         // 0..31
    const int kq = tid & 7;            // k-float4-group within chunk
    const int ks_l = kq >> 1;
    const int wA = ((kq & 1) << 1);    // + (rr>=8)
    const int wB = (kq & 1);

    // gmem base pointers
    const float* Abase = A + (size_t)(m0 + lrow) * DH + kq * 4;
    const float* Bbase = W2 + (size_t)(i0 + lrow) * DH + kq * 4;

    float acc[4][8][4];
#pragma unroll
    for (int mt = 0; mt < 4; mt++)
#pragma unroll
        for (int nt = 0; nt < 8; nt++)
#pragma unroll
            for (int e = 0; e < 4; e++) acc[mt][nt][e] = 0.f;

    float4 ra[4], rb[8];

#define LDG_CHUNK(ck)                                                      \
    {                                                                      \
        const size_t koff = (size_t)(ck) * KC;                             \
        _Pragma("unroll")                                                  \
        for (int j = 0; j < 4; j++)                                        \
            ra[j] = *reinterpret_cast<const float4*>(Abase + (size_t)j * 32 * DH + koff); \
        _Pragma("unroll")                                                  \
        for (int j = 0; j < 8; j++)                                        \
            rb[j] = *reinterpret_cast<const float4*>(Bbase + (size_t)j * 32 * DH + koff); \
    }

#define STS_CHUNK(stg)                                                     \
    {                                                                      \
        float* Ab = sm + (stg) * STAGEW;                                   \
        float* Bb = Ab + AW;                                               \
        _Pragma("unroll")                                                  \
        for (int j = 0; j < 4; j++) {                                      \
            const int row = lrow + 32 * j;                                 \
            const int rr = row & 15;                                       \
            const int mtile = row >> 4;                                    \
            const int w = wA + (rr >> 3);                                  \
            const int base = ((ks_l * 8 + mtile) * 128 + (rr & 7) * 16) + w; \
            Ab[base + 0]  = ra[j].x;                                       \
            Ab[base + 4]  = ra[j].y;                                       \
            Ab[base + 8]  = ra[j].z;                                       \
            Ab[base + 12] = ra[j].w;                                       \
        }                                                                  \
        _Pragma("unroll")                                                  \
        for (int j = 0; j < 8; j++) {                                      \
            const int irow = lrow + 32 * j;                                \
            const int ntile = irow >> 3;                                   \
            const int base = ((ks_l * 32 + ntile) * 64 + (irow & 7) * 8) + wB; \
            Bb[base + 0] = rb[j].x;                                        \
            Bb[base + 2] = rb[j].y;                                        \
            Bb[base + 4] = rb[j].z;                                        \
            Bb[base + 6] = rb[j].w;                                        \
        }                                                                  \
    }

    // prologue
    LDG_CHUNK(0);
    STS_CHUNK(0);
    if (tid < 128) sacc[tid] = 0.f;
    __syncthreads();

    for (int ck = 0; ck < NCHUNK; ck++) {
        const int cur = ck & 1;
        if (ck + 1 < NCHUNK) LDG_CHUNK(ck + 1);

        const uint32_t* Ac = reinterpret_cast<const uint32_t*>(sm + cur * STAGEW);
        const uint32_t* Bc = Ac + AW;
#pragma unroll
        for (int ks = 0; ks < 4; ks++) {
            uint32_t afr[4][4];
#pragma unroll
            for (int mt = 0; mt < 4; mt++) {
                const uint4 v = *reinterpret_cast<const uint4*>(
                    Ac + ((ks * 8 + wm * 4 + mt) * 32 + lane) * 4);
                afr[mt][0] = v.x; afr[mt][1] = v.y; afr[mt][2] = v.z; afr[mt][3] = v.w;
            }
            uint32_t bfr[8][2];
#pragma unroll
            for (int nt = 0; nt < 8; nt++) {
                const uint2 v = *reinterpret_cast<const uint2*>(
                    Bc + ((ks * 32 + wn * 8 + nt) * 32 + lane) * 2);
                bfr[nt][0] = v.x; bfr[nt][1] = v.y;
            }
#pragma unroll
            for (int mt = 0; mt < 4; mt++)
#pragma unroll
                for (int nt = 0; nt < 8; nt++)
                    mma_tf32(acc[mt][nt], afr[mt], bfr[nt]);
        }

        if (ck + 1 < NCHUNK) STS_CHUNK(cur ^ 1);
        __syncthreads();
    }

    // Epilogue: z = acc + u[i][n]; partial[m] += W3[i]*tanh(z)
    const int rbase = wm * 64 + (lane >> 2);
    const int cbase = i0 + wn * 64 + (lane & 3) * 2;
#pragma unroll
    for (int mt = 0; mt < 4; mt++) {
#pragma unroll
        for (int h = 0; h < 2; h++) {
            const int row = rbase + mt * 16 + 8 * h;
            const int n = (m0 + row) & (DN - 1);
            float s = 0.f;
#pragma unroll
            for (int nt = 0; nt < 8; nt++) {
                const int ib = cbase + nt * 8;
                const float z0 = acc[mt][nt][h * 2 + 0] + __ldg(&g_u[ib * DN + n]);
                const float z1 = acc[mt][nt][h * 2 + 1] + __ldg(&g_u[(ib + 1) * DN + n]);
                s = fmaf(__ldg(&W3[ib]), tanh_apx(z0), s);
                s = fmaf(__ldg(&W3[ib + 1]), tanh_apx(z1), s);
            }
            s += __shfl_xor_sync(0xffffffffu, s, 1);
            s += __shfl_xor_sync(0xffffffffu, s, 2);
            if ((lane & 3) == 0) atomicAdd(&sacc[row], s);
        }
    }
    __syncthreads();
    if (tid < 128) g_apart[blockIdx.x * DM + m0 + tid] = sacc[tid];
}

// ---------------------------------------------------------------------------
// Kernel 3: softmax over S per column n (sums 4 i-quarter partials + b3).
// ---------------------------------------------------------------------------
__global__ void k_softmax(float* __restrict__ alpha, const float* __restrict__ b3) {
    const int n = blockIdx.x;
    const int t = threadIdx.x;
    __shared__ float sred[16];
    const float b3v = b3[0];

    float loc[4];
    float mx = -1e30f;
#pragma unroll
    for (int qq = 0; qq < 4; qq++) {
        const int idx = (t + qq * 256) * DN + n;
        float v = b3v + g_apart[idx] + g_apart[DM + idx] +
                  g_apart[2 * DM + idx] + g_apart[3 * DM + idx];
        loc[qq] = v;
        mx = fmaxf(mx, v);
    }
#pragma unroll
    for (int off = 16; off; off >>= 1) mx = fmaxf(mx, __shfl_xor_sync(0xffffffffu, mx, off));
    if ((t & 31) == 0) sred[t >> 5] = mx;
    __syncthreads();
    if (t == 0) {
        float v = sred[0];
        for (int ww = 1; ww < 8; ww++) v = fmaxf(v, sred[ww]);
        sred[0] = v;
    }
    __syncthreads();
    mx = sred[0];

    float sum = 0.f;
#pragma unroll
    for (int qq = 0; qq < 4; qq++) {
        loc[qq] = expf(loc[qq] - mx);
        sum += loc[qq];
    }
#pragma unroll
    for (int off = 16; off; off >>= 1) sum += __shfl_xor_sync(0xffffffffu, sum, off);
    if ((t & 31) == 0) sred[8 + (t >> 5)] = sum;
    __syncthreads();
    if (t == 0) {
        float v = 0.f;
        for (int ww = 0; ww < 8; ww++) v += sred[8 + ww];
        sred[8] = v;
    }
    __syncthreads();
    const float inv = 1.0f / sred[8];
#pragma unroll
    for (int qq = 0; qq < 4; qq++) alpha[(t + qq * 256) * DN + n] = loc[qq] * inv;
}

// ---------------------------------------------------------------------------
// Kernel 4: c[n,h] = sum_s alpha[s,n] * out_e[s,n,h], 8-way MLP.
// ---------------------------------------------------------------------------
__global__ void k_ctx(const float* __restrict__ out_e, const float* __restrict__ alpha,
                      float* __restrict__ cdst) {
    const int n = blockIdx.x;
    const int h = blockIdx.y * 256 + threadIdx.x;
    __shared__ float sal[DS];
    for (int s = threadIdx.x; s < DS; s += 256) sal[s] = alpha[s * DN + n];
    __syncthreads();
    float a0 = 0.f, a1 = 0.f, a2 = 0.f, a3 = 0.f;
    float a4 = 0.f, a5 = 0.f, a6 = 0.f, a7 = 0.f;
    const float* base = out_e + (size_t)n * DH + h;
    for (int s = 0; s < DS; s += 8) {
        a0 = fmaf(sal[s + 0], base[(size_t)(s + 0) * DN * DH], a0);
        a1 = fmaf(sal[s + 1], base[(size_t)(s + 1) * DN * DH], a1);
        a2 = fmaf(sal[s + 2], base[(size_t)(s + 2) * DN * DH], a2);
        a3 = fmaf(sal[s + 3], base[(size_t)(s + 3) * DN * DH], a3);
        a4 = fmaf(sal[s + 4], base[(size_t)(s + 4) * DN * DH], a4);
        a5 = fmaf(sal[s + 5], base[(size_t)(s + 5) * DN * DH], a5);
        a6 = fmaf(sal[s + 6], base[(size_t)(s + 6) * DN * DH], a6);
        a7 = fmaf(sal[s + 7], base[(size_t)(s + 7) * DN * DH], a7);
    }
    cdst[n * DH + h] = ((a0 + a1) + (a2 + a3)) + ((a4 + a5) + (a6 + a7));
}

// ---------------------------------------------------------------------------
extern "C" void kernel_launch(void* const* d_in, const int* in_sizes, int n_in,
                              void* d_out, int out_size) {
    const float* out_e    = (const float*)d_in[0];
    const float* hidden_d = (const float*)d_in[1];
    const float* W1       = (const float*)d_in[2];
    const float* b1       = (const float*)d_in[3];
    const float* W2       = (const float*)d_in[4];
    const float* b2       = (const float*)d_in[5];
    const float* W3       = (const float*)d_in[6];
    const float* b3       = (const float*)d_in[7];
    float* out = (float*)d_out;

    float* cdst = out;
    float* alpha;
    if (out_size >= DN * DH + DM) {
        alpha = out + DN * DH;
    } else {
        void* p = nullptr;
        cudaGetSymbolAddress(&p, g_alpha_fallback);
        alpha = (float*)p;
    }

    cudaFuncSetAttribute(k_gemm, cudaFuncAttributeMaxDynamicSharedMemorySize,
                         SMEM_BYTES);

    k_u<<<DN, 256>>>(hidden_d, W1, b1, b2);
    k_gemm<<<dim3(DI / NT_CTA, DM / MT_CTA), 256, SMEM_BYTES>>>(out_e, W2, W3);
    k_softmax<<<DN, 256>>>(alpha, b3);
    k_ctx<<<dim3(DN, 4), 256>>>(out_e, alpha, cdst);
}

// round 4
// speedup vs baseline: 5.8917x; 1.7289x over previous
#include <cuda_runtime.h>
#include <cstdint>
#include <math.h>

// Problem dims
#define DS 1024
#define DN 64
#define DH 1024
#define DI 1024
#define DM (DS * DN)

// GEMM tiling
#define MT_CTA 128
#define NT_CTA 256
#define KC 32
#define NCHUNK (DH / KC)     // 32

// Fragment-packed fp16 smem (uint32 words = half2)
#define AWORDS 2048          // 2 ks * 8 mtiles * 32 lanes * 4 words
#define BWORDS 4096          // 2 ks * 32 ntiles * 32 lanes * 2 words
#define STAGEW (AWORDS + BWORDS)
#define SMEM_WORDS (2 * STAGEW + 160)
#define SMEM_BYTES (SMEM_WORDS * 4)

// Scratch
__device__ float g_u[DI * DN];       // u transposed: [i][n]
__device__ float g_apart[4 * DM];    // per-i-quarter partial scores
__device__ float g_cpart[4 * DN * DH];
__device__ float g_alpha_fallback[DM];

__device__ __forceinline__ float tanh_apx(float x) {
    float y;
    asm("tanh.approx.f32 %0, %1;" : "=f"(y) : "f"(x));
    return y;
}
__device__ __forceinline__ uint32_t f2h2(float lo, float hi) {
    uint32_t r;
    asm("cvt.rn.f16x2.f32 %0, %1, %2;" : "=r"(r) : "f"(hi), "f"(lo));
    return r;
}
__device__ __forceinline__ void mma_f16(float* d, const uint32_t* a, const uint32_t* b) {
    asm volatile(
        "mma.sync.aligned.m16n8k16.row.col.f32.f16.f16.f32 "
        "{%0,%1,%2,%3}, {%4,%5,%6,%7}, {%8,%9}, {%0,%1,%2,%3};"
        : "+f"(d[0]), "+f"(d[1]), "+f"(d[2]), "+f"(d[3])
        : "r"(a[0]), "r"(a[1]), "r"(a[2]), "r"(a[3]), "r"(b[0]), "r"(b[1]));
}

// ---------------------------------------------------------------------------
// Kernel 1: u_t[i][n] = b1[i] + b2[i] + dot(hidden_d[n,:], W1[i,:])
// ---------------------------------------------------------------------------
__global__ void k_u(const float* __restrict__ hd, const float* __restrict__ W1,
                    const float* __restrict__ b1, const float* __restrict__ b2) {
    __shared__ float sh[DH];
    const int n = blockIdx.x;
    for (int h = threadIdx.x; h < DH; h += blockDim.x) sh[h] = hd[n * DH + h];
    __syncthreads();
    for (int i = threadIdx.x; i < DI; i += blockDim.x) {
        const float4* w = reinterpret_cast<const float4*>(W1 + (size_t)i * DH);
        const float4* sv = reinterpret_cast<const float4*>(sh);
        float ax = 0.f, ay = 0.f, az = 0.f, aw = 0.f;
#pragma unroll 4
        for (int h4 = 0; h4 < DH / 4; h4++) {
            float4 a = sv[h4];
            float4 b = w[h4];
            ax = fmaf(a.x, b.x, ax);
            ay = fmaf(a.y, b.y, ay);
            az = fmaf(a.z, b.z, az);
            aw = fmaf(a.w, b.w, aw);
        }
        g_u[i * DN + n] = (ax + ay) + (az + aw) + b1[i] + b2[i];
    }
}

// ---------------------------------------------------------------------------
// Kernel 2: fp16 mma.sync fused GEMM + tanh + W3 reduction.
// grid (4 i-quarters, 512 m-blocks), 256 threads.
// CTA 128m x 256i, K=1024 in 32 chunks, double-buffered fragment-packed fp16.
// ---------------------------------------------------------------------------
__global__ __launch_bounds__(256, 1) void k_gemm(
    const float* __restrict__ A,    // out_e as [65536, 1024]
    const float* __restrict__ W2,
    const float* __restrict__ W3) {
    extern __shared__ uint32_t smu[];
    float* sacc = reinterpret_cast<float*>(smu + 2 * STAGEW);

    const int tid = threadIdx.x;
    const int lane = tid & 31;
    const int wid = tid >> 5;
    const int wm = wid >> 2;   // 0..1
    const int wn = wid & 3;    // 0..3
    const int i0 = blockIdx.x * NT_CTA;
    const int m0 = blockIdx.y * MT_CTA;

    // loader mapping
    const int lrow = tid >> 3;         // 0..31
    const int kq = tid & 7;            // float4 index within 32-float chunk

    const float* Abase = A + (size_t)(m0 + lrow) * DH + kq * 4;
    const float* Bbase = W2 + (size_t)(i0 + lrow) * DH + kq * 4;

    // precomputed packing offsets
    const int ksl = kq >> 2;
    const int pq = kq & 3;
    const int a_lane_k = (pq & 1) * 2;          // (pp0 & 3)
    const int a_word_k = 2 * (pq >> 1);         // 2*(pp0>>2)
    const int b_word = (kq & 3) >> 1;
    const int b_lane_k = (kq & 1) * 2;

    float acc[4][8][4];
#pragma unroll
    for (int mt = 0; mt < 4; mt++)
#pragma unroll
        for (int nt = 0; nt < 8; nt++)
#pragma unroll
            for (int e = 0; e < 4; e++) acc[mt][nt][e] = 0.f;

    float4 ra[4], rb[8];

#define LDG_CHUNK(ck)                                                      \
    {                                                                      \
        const size_t koff = (size_t)(ck) * KC;                             \
        _Pragma("unroll")                                                  \
        for (int j = 0; j < 4; j++)                                        \
            ra[j] = *reinterpret_cast<const float4*>(Abase + (size_t)j * 32 * DH + koff); \
        _Pragma("unroll")                                                  \
        for (int j = 0; j < 8; j++)                                        \
            rb[j] = *reinterpret_cast<const float4*>(Bbase + (size_t)j * 32 * DH + koff); \
    }

#define STS_CHUNK(stg)                                                     \
    {                                                                      \
        uint32_t* Ab = smu + (stg) * STAGEW;                               \
        uint32_t* Bb = Ab + AWORDS;                                        \
        _Pragma("unroll")                                                  \
        for (int j = 0; j < 4; j++) {                                      \
            const int m = lrow + 32 * j;                                   \
            const int lane0 = (m & 7) * 4 + a_lane_k;                      \
            const int word = ((m >> 3) & 1) + a_word_k;                    \
            const int idx = ((ksl * 8 + (m >> 4)) * 32 + lane0) * 4 + word;\
            Ab[idx]     = f2h2(ra[j].x, ra[j].y);                          \
            Ab[idx + 4] = f2h2(ra[j].z, ra[j].w);                          \
        }                                                                  \
        _Pragma("unroll")                                                  \
        for (int j = 0; j < 8; j++) {                                      \
            const int irow = lrow + 32 * j;                                \
            const int lane0 = b_lane_k + 4 * (irow & 7);                   \
            const int idx = ((ksl * 32 + (irow >> 3)) * 32 + lane0) * 2 + b_word; \
            Bb[idx]     = f2h2(rb[j].x, rb[j].y);                          \
            Bb[idx + 2] = f2h2(rb[j].z, rb[j].w);                          \
        }                                                                  \
    }

    LDG_CHUNK(0);
    STS_CHUNK(0);
    if (tid < 128) sacc[tid] = 0.f;
    __syncthreads();

    for (int ck = 0; ck < NCHUNK; ck++) {
        const int cur = ck & 1;
        if (ck + 1 < NCHUNK) LDG_CHUNK(ck + 1);

        const uint32_t* Ac = smu + cur * STAGEW;
        const uint32_t* Bc = Ac + AWORDS;
#pragma unroll
        for (int ks = 0; ks < 2; ks++) {
            uint32_t afr[4][4];
#pragma unroll
            for (int mt = 0; mt < 4; mt++) {
                const uint4 v = *reinterpret_cast<const uint4*>(
                    Ac + ((ks * 8 + wm * 4 + mt) * 32 + lane) * 4);
                afr[mt][0] = v.x; afr[mt][1] = v.y; afr[mt][2] = v.z; afr[mt][3] = v.w;
            }
            uint32_t bfr[8][2];
#pragma unroll
            for (int nt = 0; nt < 8; nt++) {
                const uint2 v = *reinterpret_cast<const uint2*>(
                    Bc + ((ks * 32 + wn * 8 + nt) * 32 + lane) * 2);
                bfr[nt][0] = v.x; bfr[nt][1] = v.y;
            }
#pragma unroll
            for (int mt = 0; mt < 4; mt++)
#pragma unroll
                for (int nt = 0; nt < 8; nt++)
                    mma_f16(acc[mt][nt], afr[mt], bfr[nt]);
        }

        if (ck + 1 < NCHUNK) STS_CHUNK(cur ^ 1);
        __syncthreads();
    }

    // Epilogue: z = acc + u[i][n]; partial[m] += W3[i]*tanh(z)
    const int rbase = wm * 64 + (lane >> 2);
    const int cbase = i0 + wn * 64 + (lane & 3) * 2;
#pragma unroll
    for (int mt = 0; mt < 4; mt++) {
#pragma unroll
        for (int h = 0; h < 2; h++) {
            const int row = rbase + mt * 16 + 8 * h;
            const int n = (m0 + row) & (DN - 1);
            float s = 0.f;
#pragma unroll
            for (int nt = 0; nt < 8; nt++) {
                const int ib = cbase + nt * 8;
                const float z0 = acc[mt][nt][h * 2 + 0] + __ldg(&g_u[ib * DN + n]);
                const float z1 = acc[mt][nt][h * 2 + 1] + __ldg(&g_u[(ib + 1) * DN + n]);
                s = fmaf(__ldg(&W3[ib]), tanh_apx(z0), s);
                s = fmaf(__ldg(&W3[ib + 1]), tanh_apx(z1), s);
            }
            s += __shfl_xor_sync(0xffffffffu, s, 1);
            s += __shfl_xor_sync(0xffffffffu, s, 2);
            if ((lane & 3) == 0) atomicAdd(&sacc[row], s);
        }
    }
    __syncthreads();
    if (tid < 128) g_apart[blockIdx.x * DM + m0 + tid] = sacc[tid];
}

// ---------------------------------------------------------------------------
// Kernel 3: softmax over S per column n (sums 4 i-quarter partials + b3).
// ---------------------------------------------------------------------------
__global__ void k_softmax(float* __restrict__ alpha, const float* __restrict__ b3) {
    const int n = blockIdx.x;
    const int t = threadIdx.x;
    __shared__ float sred[16];
    const float b3v = b3[0];

    float loc[4];
    float mx = -1e30f;
#pragma unroll
    for (int qq = 0; qq < 4; qq++) {
        const int idx = (t + qq * 256) * DN + n;
        float v = b3v + g_apart[idx] + g_apart[DM + idx] +
                  g_apart[2 * DM + idx] + g_apart[3 * DM + idx];
        loc[qq] = v;
        mx = fmaxf(mx, v);
    }
#pragma unroll
    for (int off = 16; off; off >>= 1) mx = fmaxf(mx, __shfl_xor_sync(0xffffffffu, mx, off));
    if ((t & 31) == 0) sred[t >> 5] = mx;
    __syncthreads();
    if (t == 0) {
        float v = sred[0];
        for (int ww = 1; ww < 8; ww++) v = fmaxf(v, sred[ww]);
        sred[0] = v;
    }
    __syncthreads();
    mx = sred[0];

    float sum = 0.f;
#pragma unroll
    for (int qq = 0; qq < 4; qq++) {
        loc[qq] = expf(loc[qq] - mx);
        sum += loc[qq];
    }
#pragma unroll
    for (int off = 16; off; off >>= 1) sum += __shfl_xor_sync(0xffffffffu, sum, off);
    if ((t & 31) == 0) sred[8 + (t >> 5)] = sum;
    __syncthreads();
    if (t == 0) {
        float v = 0.f;
        for (int ww = 0; ww < 8; ww++) v += sred[8 + ww];
        sred[8] = v;
    }
    __syncthreads();
    const float inv = 1.0f / sred[8];
#pragma unroll
    for (int qq = 0; qq < 4; qq++) alpha[(t + qq * 256) * DN + n] = loc[qq] * inv;
}

// ---------------------------------------------------------------------------
// Kernel 4a: partial context, s-split 4 ways for occupancy.
// grid (64 n, 4 hchunk, 4 schunk), 256 threads.
// ---------------------------------------------------------------------------
__global__ void k_ctx_part(const float* __restrict__ out_e,
                           const float* __restrict__ alpha) {
    const int n = blockIdx.x;
    const int h = blockIdx.y * 256 + threadIdx.x;
    const int s0 = blockIdx.z * 256;
    __shared__ float sal[256];
    if (threadIdx.x < 256) sal[threadIdx.x] = alpha[(s0 + threadIdx.x) * DN + n];
    __syncthreads();
    float a0 = 0.f, a1 = 0.f, a2 = 0.f, a3 = 0.f;
    float a4 = 0.f, a5 = 0.f, a6 = 0.f, a7 = 0.f;
    const float* base = out_e + (size_t)(s0) * DN * DH + (size_t)n * DH + h;
    for (int s = 0; s < 256; s += 8) {
        a0 = fmaf(sal[s + 0], base[(size_t)(s + 0) * DN * DH], a0);
        a1 = fmaf(sal[s + 1], base[(size_t)(s + 1) * DN * DH], a1);
        a2 = fmaf(sal[s + 2], base[(size_t)(s + 2) * DN * DH], a2);
        a3 = fmaf(sal[s + 3], base[(size_t)(s + 3) * DN * DH], a3);
        a4 = fmaf(sal[s + 4], base[(size_t)(s + 4) * DN * DH], a4);
        a5 = fmaf(sal[s + 5], base[(size_t)(s + 5) * DN * DH], a5);
        a6 = fmaf(sal[s + 6], base[(size_t)(s + 6) * DN * DH], a6);
        a7 = fmaf(sal[s + 7], base[(size_t)(s + 7) * DN * DH], a7);
    }
    g_cpart[(blockIdx.z * DN + n) * DH + h] =
        ((a0 + a1) + (a2 + a3)) + ((a4 + a5) + (a6 + a7));
}

// Kernel 4b: sum the 4 s-partials.
__global__ void k_ctx_sum(float* __restrict__ cdst) {
    const int idx = blockIdx.x * 256 + threadIdx.x;
    cdst[idx] = (g_cpart[idx] + g_cpart[DN * DH + idx]) +
                (g_cpart[2 * DN * DH + idx] + g_cpart[3 * DN * DH + idx]);
}

// ---------------------------------------------------------------------------
extern "C" void kernel_launch(void* const* d_in, const int* in_sizes, int n_in,
                              void* d_out, int out_size) {
    const float* out_e    = (const float*)d_in[0];
    const float* hidden_d = (const float*)d_in[1];
    const float* W1       = (const float*)d_in[2];
    const float* b1       = (const float*)d_in[3];
    const float* W2       = (const float*)d_in[4];
    const float* b2       = (const float*)d_in[5];
    const float* W3       = (const float*)d_in[6];
    const float* b3       = (const float*)d_in[7];
    float* out = (float*)d_out;

    float* cdst = out;
    float* alpha;
    if (out_size >= DN * DH + DM) {
        alpha = out + DN * DH;
    } else {
        void* p = nullptr;
        cudaGetSymbolAddress(&p, g_alpha_fallback);
        alpha = (float*)p;
    }

    cudaFuncSetAttribute(k_gemm, cudaFuncAttributeMaxDynamicSharedMemorySize,
                         SMEM_BYTES);

    k_u<<<DN, 256>>>(hidden_d, W1, b1, b2);
    k_gemm<<<dim3(DI / NT_CTA, DM / MT_CTA), 256, SMEM_BYTES>>>(out_e, W2, W3);
    k_softmax<<<DN, 256>>>(alpha, b3);
    k_ctx_part<<<dim3(DN, 4, 4), 256>>>(out_e, alpha);
    k_ctx_sum<<<DN * DH / 256, 256>>>(cdst);
}